// round 12
// baseline (speedup 1.0000x reference)
#include <cuda_runtime.h>
#include <math.h>

#define AD 128
#define SD 64
#define NLAYERS 4
#define MAXN 50000
#define MAXE 800000

// ---------------- device scratch (no allocation allowed) ----------------
__device__ float d_h2[MAXN * AD];      // GEMM output (GCN)
__device__ float d_hbuf[MAXN * AD];    // GCN layer activation
__device__ float d_t[MAXN * SD];       // w2(g)
__device__ float d_outb[MAXN * SD];    // w1(g)
__device__ float d_gbuf[MAXN * SD];    // GNA layer activation
__device__ float d_ta[MAXN];           // t . a
__device__ float d_dinv[MAXN];
__device__ int   d_deg[MAXN];
__device__ int   d_fill[MAXN];
__device__ int   d_row[MAXE];
__device__ int   d_col[MAXE];
__device__ int   d_esrc[MAXE];         // CSR: src node of each edge, grouped by dst
__device__ float d_enorm[MAXE];        // CSR-ordered GCN norm
__device__ int   d_rowptr[MAXN + 1];
__device__ int   d_bsum[64];
__device__ int   d_is64;               // edge_index dtype flag (1 = int64, 0 = int32)

// ---------------- helpers ----------------
__device__ __forceinline__ float gelu_exact(float x) {
    return 0.5f * x * (1.0f + erff(x * 0.7071067811865475f));
}

// ---------------- setup kernels ----------------
// Detect edge_index dtype: for int64 values < 2^31, every odd int32 word is 0.
// For int32 layout those words are random node ids. One block, deterministic.
__global__ void k_detect(const int* __restrict__ ei32, int E) {
    __shared__ int found;
    if (threadIdx.x == 0) found = 0;
    __syncthreads();
    int nz = 0;
    int samples = (E < 4096) ? E : 4096;
    for (int i = threadIdx.x; i < samples; i += blockDim.x)
        if (ei32[2 * i + 1] != 0) nz = 1;
    if (__syncthreads_or(nz)) { if (threadIdx.x == 0) found = 1; }
    __syncthreads();
    if (threadIdx.x == 0) d_is64 = found ? 0 : 1;
}

__global__ void k_zero(int n) {
    int i = blockIdx.x * blockDim.x + threadIdx.x;
    if (i < n) { d_deg[i] = 0; d_fill[i] = 0; }
}

__global__ void k_prep(const void* __restrict__ ei, int E) {
    int e = blockIdx.x * blockDim.x + threadIdx.x;
    if (e >= E) return;
    int r, c;
    if (d_is64) {
        const long long* p = (const long long*)ei;
        r = (int)p[e];
        c = (int)p[E + e];
    } else {
        const int* p = (const int*)ei;
        r = p[e];
        c = p[E + e];
    }
    d_row[e] = r;
    d_col[e] = c;
    atomicAdd(&d_deg[c], 1);
}

__global__ void k_dinv(int n) {
    int i = blockIdx.x * blockDim.x + threadIdx.x;
    if (i < n) d_dinv[i] = rsqrtf((float)d_deg[i] + 1.0f);   // +1 for self loop
}

// ---- exclusive prefix sum over deg -> rowptr (3 kernels) ----
__global__ void k_scan1(int n) {
    __shared__ int sm[1024];
    int i = blockIdx.x * 1024 + threadIdx.x;
    int v = (i < n) ? d_deg[i] : 0;
    sm[threadIdx.x] = v;
    __syncthreads();
    for (int off = 1; off < 1024; off <<= 1) {
        int t = (threadIdx.x >= off) ? sm[threadIdx.x - off] : 0;
        __syncthreads();
        sm[threadIdx.x] += t;
        __syncthreads();
    }
    if (i < n) d_rowptr[i + 1] = sm[threadIdx.x];
    if (threadIdx.x == 1023) d_bsum[blockIdx.x] = sm[1023];
}

__global__ void k_scan2(int nb) {
    if (threadIdx.x == 0) {
        int acc = 0;
        for (int b = 0; b < nb; b++) { int v = d_bsum[b]; d_bsum[b] = acc; acc += v; }
        d_rowptr[0] = 0;
    }
}

__global__ void k_scan3(int n) {
    int i = blockIdx.x * blockDim.x + threadIdx.x;
    if (i < n) d_rowptr[i + 1] += d_bsum[i >> 10];
}

// fill CSR: edges grouped by dst; also precompute GCN norm in CSR order
__global__ void k_fill(int E) {
    int e = blockIdx.x * blockDim.x + threadIdx.x;
    if (e >= E) return;
    int r = d_row[e];
    int c = d_col[e];
    int pos = d_rowptr[c] + atomicAdd(&d_fill[c], 1);
    d_esrc[pos]  = r;
    d_enorm[pos] = d_dinv[r] * d_dinv[c];
}

// ---------------- SIMT GEMM: C[n,D] = A[n,D] @ W[D,D] (+ bias) ----------------
template<int D, int KB>
__global__ __launch_bounds__(256)
void gemm_kernel(const float* __restrict__ A, const float* __restrict__ W,
                 const float* __restrict__ bias, float* __restrict__ C, int n)
{
    constexpr int COLG = D / 16;        // column groups (16 cols per thread)
    constexpr int ROWG = 256 / COLG;    // row groups
    constexpr int BM   = ROWG * 4;      // rows per block (4 per thread)
    constexpr int LDA  = KB + 1;        // padded to avoid bank conflicts
    extern __shared__ float smem[];
    float* Ws = smem;                   // D*D
    float* As = smem + D * D;           // BM * LDA

    const int tid = threadIdx.x;
    const int cg = tid % COLG;
    const int rg = tid / COLG;
    const int rowbase = blockIdx.x * BM;

    // stage full W into shared memory
    {
        const float4* Wg = reinterpret_cast<const float4*>(W);
        float4* Wsm = reinterpret_cast<float4*>(Ws);
        for (int i = tid; i < D * D / 4; i += 256) Wsm[i] = Wg[i];
    }

    float acc[4][16];
    #pragma unroll
    for (int i = 0; i < 4; i++)
        #pragma unroll
        for (int j = 0; j < 16; j++) acc[i][j] = 0.0f;

    for (int kb = 0; kb < D; kb += KB) {
        __syncthreads();
        // stage A tile BM x KB
        for (int i = tid; i < BM * KB / 4; i += 256) {
            int r  = i / (KB / 4);
            int kc = (i % (KB / 4)) * 4;
            int gr = rowbase + r;
            float4 v = make_float4(0.f, 0.f, 0.f, 0.f);
            if (gr < n)
                v = *reinterpret_cast<const float4*>(A + (size_t)gr * D + kb + kc);
            As[r * LDA + kc + 0] = v.x;
            As[r * LDA + kc + 1] = v.y;
            As[r * LDA + kc + 2] = v.z;
            As[r * LDA + kc + 3] = v.w;
        }
        __syncthreads();
        #pragma unroll 8
        for (int k = 0; k < KB; k++) {
            float a0 = As[(rg * 4 + 0) * LDA + k];
            float a1 = As[(rg * 4 + 1) * LDA + k];
            float a2 = As[(rg * 4 + 2) * LDA + k];
            float a3 = As[(rg * 4 + 3) * LDA + k];
            const float* wr = Ws + (kb + k) * D + cg * 4;
            #pragma unroll
            for (int j4 = 0; j4 < 4; j4++) {
                float4 w = *reinterpret_cast<const float4*>(wr + j4 * (4 * COLG));
                acc[0][j4*4+0] += a0 * w.x; acc[0][j4*4+1] += a0 * w.y;
                acc[0][j4*4+2] += a0 * w.z; acc[0][j4*4+3] += a0 * w.w;
                acc[1][j4*4+0] += a1 * w.x; acc[1][j4*4+1] += a1 * w.y;
                acc[1][j4*4+2] += a1 * w.z; acc[1][j4*4+3] += a1 * w.w;
                acc[2][j4*4+0] += a2 * w.x; acc[2][j4*4+1] += a2 * w.y;
                acc[2][j4*4+2] += a2 * w.z; acc[2][j4*4+3] += a2 * w.w;
                acc[3][j4*4+0] += a3 * w.x; acc[3][j4*4+1] += a3 * w.y;
                acc[3][j4*4+2] += a3 * w.z; acc[3][j4*4+3] += a3 * w.w;
            }
        }
    }

    #pragma unroll
    for (int i = 0; i < 4; i++) {
        int gr = rowbase + rg * 4 + i;
        if (gr >= n) continue;
        #pragma unroll
        for (int j4 = 0; j4 < 4; j4++) {
            int c = cg * 4 + j4 * (4 * COLG);
            float4 v;
            v.x = acc[i][j4*4+0]; v.y = acc[i][j4*4+1];
            v.z = acc[i][j4*4+2]; v.w = acc[i][j4*4+3];
            if (bias) {
                v.x += bias[c+0]; v.y += bias[c+1];
                v.z += bias[c+2]; v.w += bias[c+3];
            }
            *reinterpret_cast<float4*>(C + (size_t)gr * D + c) = v;
        }
    }
}

// ---------------- GCN aggregation: warp per dst node, gather-only ----------------
// out[v] = (optional gelu)( bias + dinv[v]^2 * h2[v] + sum_e norm_e * h2[src_e] )
__global__ __launch_bounds__(256)
void k_gcn_agg(const float* __restrict__ h2, const float* __restrict__ bias,
               float* __restrict__ outp, int n, int dogelu)
{
    int gid = blockIdx.x * blockDim.x + threadIdx.x;
    int v = gid >> 5;
    if (v >= n) return;
    int lane = gid & 31;
    int c = lane << 2;

    int beg = d_rowptr[v];
    int end = d_rowptr[v + 1];
    float di = d_dinv[v];
    float di2 = di * di;

    float4 acc = *reinterpret_cast<const float4*>(h2 + (size_t)v * AD + c);
    float4 bs  = *reinterpret_cast<const float4*>(bias + c);
    acc.x = bs.x + di2 * acc.x;
    acc.y = bs.y + di2 * acc.y;
    acc.z = bs.z + di2 * acc.z;
    acc.w = bs.w + di2 * acc.w;

    for (int e = beg; e < end; e++) {
        int src  = d_esrc[e];
        float nv = d_enorm[e];
        float4 h = *reinterpret_cast<const float4*>(h2 + (size_t)src * AD + c);
        acc.x += nv * h.x; acc.y += nv * h.y;
        acc.z += nv * h.z; acc.w += nv * h.w;
    }

    if (dogelu) {
        acc.x = gelu_exact(acc.x); acc.y = gelu_exact(acc.y);
        acc.z = gelu_exact(acc.z); acc.w = gelu_exact(acc.w);
    }
    *reinterpret_cast<float4*>(outp + (size_t)v * AD + c) = acc;
}

// ---------------- GNA kernels ----------------
// per-node: ta[v] = t[v] . a   (warp per node)
__global__ void k_ta(const float* __restrict__ a, int n) {
    int gid = blockIdx.x * blockDim.x + threadIdx.x;
    int w = gid >> 5;
    int lane = gid & 31;
    if (w >= n) return;
    float p = d_t[(size_t)w * SD + lane] * a[lane]
            + d_t[(size_t)w * SD + 32 + lane] * a[32 + lane];
    #pragma unroll
    for (int o = 16; o; o >>= 1) p += __shfl_xor_sync(0xffffffffu, p, o);
    if (lane == 0) d_ta[w] = p;
}

// warp per dst node: edge-softmax attention aggregation, fully in registers.
// amax = max(0, max_e (ta[v]-ta[src]))   (self loop alpha = 0)
// msg  = (sum_e e_e * t[src] + e_self * t[v]) / (sum e + 1e-16)
// gout = gelu(w1out + msg)
__global__ __launch_bounds__(256)
void k_gna_agg(float* __restrict__ gout, int n)
{
    int gid = blockIdx.x * blockDim.x + threadIdx.x;
    int v = gid >> 5;
    if (v >= n) return;
    int lane = gid & 31;

    int beg = d_rowptr[v];
    int end = d_rowptr[v + 1];
    float tav = d_ta[v];

    // pass 1: amax (lane-strided + warp reduce), self-loop contributes 0
    float m = 0.0f;
    for (int e = beg + lane; e < end; e += 32)
        m = fmaxf(m, tav - d_ta[d_esrc[e]]);
    #pragma unroll
    for (int o = 16; o; o >>= 1) m = fmaxf(m, __shfl_xor_sync(0xffffffffu, m, o));

    // pass 2: unnormalized weighted sum + denom (denom redundantly per lane)
    float a0 = 0.0f, a1 = 0.0f, denom = 0.0f;
    for (int e = beg; e < end; e++) {
        int src = d_esrc[e];
        float wgt = expf(tav - d_ta[src] - m);
        denom += wgt;
        a0 += wgt * d_t[(size_t)src * SD + lane];
        a1 += wgt * d_t[(size_t)src * SD + 32 + lane];
    }
    float wself = expf(-m);
    denom += wself;
    a0 += wself * d_t[(size_t)v * SD + lane];
    a1 += wself * d_t[(size_t)v * SD + 32 + lane];

    float inv = 1.0f / (denom + 1e-16f);
    size_t o = (size_t)v * SD;
    gout[o + lane]      = gelu_exact(d_outb[o + lane]      + a0 * inv);
    gout[o + 32 + lane] = gelu_exact(d_outb[o + 32 + lane] + a1 * inv);
}

// ---------------- host orchestration ----------------
extern "C" void kernel_launch(void* const* d_in, const int* in_sizes, int n_in,
                              void* d_out, int out_size) {
    const float* x     = (const float*)d_in[0];
    const float* s     = (const float*)d_in[1];
    const void*  ei    = (const void*)d_in[2];
    const float* gcn_W = (const float*)d_in[3];
    const float* gcn_b = (const float*)d_in[4];
    const float* w1W   = (const float*)d_in[5];
    const float* w1b   = (const float*)d_in[6];
    const float* w2W   = (const float*)d_in[7];
    const float* w2b   = (const float*)d_in[8];
    const float* ga    = (const float*)d_in[9];
    float* outp = (float*)d_out;

    const int n = in_sizes[0] / AD;
    const int E = in_sizes[2] / 2;

    void *p_h2, *p_hbuf, *p_t, *p_outb, *p_gbuf;
    cudaGetSymbolAddress(&p_h2,   d_h2);
    cudaGetSymbolAddress(&p_hbuf, d_hbuf);
    cudaGetSymbolAddress(&p_t,    d_t);
    cudaGetSymbolAddress(&p_outb, d_outb);
    cudaGetSymbolAddress(&p_gbuf, d_gbuf);

    const int SM128 = AD * AD * 4 + 128 * 33 * 4;   // 82432 B
    const int SM64  = SD * SD * 4 + 256 * 65 * 4;   // 82944 B
    cudaFuncSetAttribute(gemm_kernel<128,32>, cudaFuncAttributeMaxDynamicSharedMemorySize, SM128);
    cudaFuncSetAttribute(gemm_kernel<64,64>,  cudaFuncAttributeMaxDynamicSharedMemorySize, SM64);

    const int TB = 256;
    auto gb = [](int total, int tb) { return (total + tb - 1) / tb; };

    // ---- setup: dtype probe, degrees, dinv, CSR build ----
    k_detect<<<1, 256>>>((const int*)ei, E);
    k_zero<<<gb(n, TB), TB>>>(n);
    k_prep<<<gb(E, TB), TB>>>(ei, E);
    k_dinv<<<gb(n, TB), TB>>>(n);
    int nscan = gb(n, 1024);
    k_scan1<<<nscan, 1024>>>(n);
    k_scan2<<<1, 64>>>(nscan);
    k_scan3<<<gb(n, TB), TB>>>(n);
    k_fill<<<gb(E, TB), TB>>>(E);

    // ---- GCN branch ----
    const float* hcur = x;
    for (int i = 0; i < NLAYERS; i++) {
        gemm_kernel<128,32><<<gb(n, 128), 256, SM128>>>(
            hcur, gcn_W + (size_t)i * AD * AD, nullptr, (float*)p_h2, n);
        float* aggout = (i == NLAYERS - 1) ? outp : (float*)p_hbuf;
        k_gcn_agg<<<gb(n * 32, TB), TB>>>((const float*)p_h2,
                                          gcn_b + (size_t)i * AD,
                                          aggout, n, (i < NLAYERS - 1) ? 1 : 0);
        hcur = (const float*)p_hbuf;
    }

    // ---- GNA branch ----
    const float* gcur = s;
    for (int i = 0; i < NLAYERS; i++) {
        gemm_kernel<64,64><<<gb(n, 256), 256, SM64>>>(
            gcur, w2W + (size_t)i * SD * SD, w2b + (size_t)i * SD, (float*)p_t, n);
        gemm_kernel<64,64><<<gb(n, 256), 256, SM64>>>(
            gcur, w1W + (size_t)i * SD * SD, w1b + (size_t)i * SD, (float*)p_outb, n);
        k_ta<<<gb(n * 32, TB), TB>>>(ga + (size_t)i * SD, n);
        float* gout = (i == NLAYERS - 1) ? (outp + (size_t)n * AD) : (float*)p_gbuf;
        k_gna_agg<<<gb(n * 32, TB), TB>>>(gout, n);
        gcur = (const float*)p_gbuf;
    }
}

// round 14
// speedup vs baseline: 1.2690x; 1.2690x over previous
#include <cuda_runtime.h>
#include <math.h>

#define AD 128
#define SD 64
#define NLAYERS 4
#define MAXN 50000
#define MAXE 800000

// ---------------- device scratch (no allocation allowed) ----------------
__device__ float d_h2[MAXN * AD];      // GEMM output (GCN)
__device__ float d_hbuf[MAXN * AD];    // GCN layer activation
__device__ float d_t[MAXN * SD];       // w2(g)
__device__ float d_outb[MAXN * SD];    // w1(g)
__device__ float d_gbuf[MAXN * SD];    // GNA layer activation
__device__ float d_ta[MAXN];           // t . a
__device__ float d_dinv[MAXN];
__device__ int   d_deg[MAXN];
__device__ int   d_fill[MAXN];
__device__ int   d_row[MAXE];
__device__ int   d_col[MAXE];
__device__ int   d_esrc[MAXE];         // CSR: src node of each edge, grouped by dst
__device__ float d_enorm[MAXE];        // CSR-ordered GCN norm
__device__ int   d_rowptr[MAXN + 1];
__device__ int   d_bsum[64];
__device__ int   d_is64;               // edge_index dtype flag (1 = int64, 0 = int32)

// ---------------- helpers ----------------
__device__ __forceinline__ float gelu_exact(float x) {
    return 0.5f * x * (1.0f + erff(x * 0.7071067811865475f));
}

// ---------------- setup kernels ----------------
__global__ void k_detect(const int* __restrict__ ei32, int E) {
    __shared__ int found;
    if (threadIdx.x == 0) found = 0;
    __syncthreads();
    int nz = 0;
    int samples = (E < 4096) ? E : 4096;
    for (int i = threadIdx.x; i < samples; i += blockDim.x)
        if (ei32[2 * i + 1] != 0) nz = 1;
    if (__syncthreads_or(nz)) { if (threadIdx.x == 0) found = 1; }
    __syncthreads();
    if (threadIdx.x == 0) d_is64 = found ? 0 : 1;
}

__global__ void k_zero(int n) {
    int i = blockIdx.x * blockDim.x + threadIdx.x;
    if (i < n) { d_deg[i] = 0; d_fill[i] = 0; }
}

__global__ void k_prep(const void* __restrict__ ei, int E) {
    int e = blockIdx.x * blockDim.x + threadIdx.x;
    if (e >= E) return;
    int r, c;
    if (d_is64) {
        const long long* p = (const long long*)ei;
        r = (int)p[e];
        c = (int)p[E + e];
    } else {
        const int* p = (const int*)ei;
        r = p[e];
        c = p[E + e];
    }
    d_row[e] = r;
    d_col[e] = c;
    atomicAdd(&d_deg[c], 1);
}

__global__ void k_dinv(int n) {
    int i = blockIdx.x * blockDim.x + threadIdx.x;
    if (i < n) d_dinv[i] = rsqrtf((float)d_deg[i] + 1.0f);   // +1 for self loop
}

// ---- exclusive prefix sum over deg -> rowptr (3 kernels) ----
__global__ void k_scan1(int n) {
    __shared__ int sm[1024];
    int i = blockIdx.x * 1024 + threadIdx.x;
    int v = (i < n) ? d_deg[i] : 0;
    sm[threadIdx.x] = v;
    __syncthreads();
    for (int off = 1; off < 1024; off <<= 1) {
        int t = (threadIdx.x >= off) ? sm[threadIdx.x - off] : 0;
        __syncthreads();
        sm[threadIdx.x] += t;
        __syncthreads();
    }
    if (i < n) d_rowptr[i + 1] = sm[threadIdx.x];
    if (threadIdx.x == 1023) d_bsum[blockIdx.x] = sm[1023];
}

__global__ void k_scan2(int nb) {
    if (threadIdx.x == 0) {
        int acc = 0;
        for (int b = 0; b < nb; b++) { int v = d_bsum[b]; d_bsum[b] = acc; acc += v; }
        d_rowptr[0] = 0;
    }
}

__global__ void k_scan3(int n) {
    int i = blockIdx.x * blockDim.x + threadIdx.x;
    if (i < n) d_rowptr[i + 1] += d_bsum[i >> 10];
}

__global__ void k_fill(int E) {
    int e = blockIdx.x * blockDim.x + threadIdx.x;
    if (e >= E) return;
    int r = d_row[e];
    int c = d_col[e];
    int pos = d_rowptr[c] + atomicAdd(&d_fill[c], 1);
    d_esrc[pos]  = r;
    d_enorm[pos] = d_dinv[r] * d_dinv[c];
}

// ---------------- SIMT GEMM: C[n,D] = A[n,D] @ W[D,D] (+ bias) ----------------
template<int D, int KB>
__global__ __launch_bounds__(256)
void gemm_kernel(const float* __restrict__ A, const float* __restrict__ W,
                 const float* __restrict__ bias, float* __restrict__ C, int n)
{
    constexpr int COLG = D / 16;
    constexpr int ROWG = 256 / COLG;
    constexpr int BM   = ROWG * 4;
    constexpr int LDA  = KB + 1;
    extern __shared__ float smem[];
    float* Ws = smem;                   // D*D
    float* As = smem + D * D;           // BM * LDA

    const int tid = threadIdx.x;
    const int cg = tid % COLG;
    const int rg = tid / COLG;
    const int rowbase = blockIdx.x * BM;

    {
        const float4* Wg = reinterpret_cast<const float4*>(W);
        float4* Wsm = reinterpret_cast<float4*>(Ws);
        for (int i = tid; i < D * D / 4; i += 256) Wsm[i] = Wg[i];
    }

    float acc[4][16];
    #pragma unroll
    for (int i = 0; i < 4; i++)
        #pragma unroll
        for (int j = 0; j < 16; j++) acc[i][j] = 0.0f;

    for (int kb = 0; kb < D; kb += KB) {
        __syncthreads();
        for (int i = tid; i < BM * KB / 4; i += 256) {
            int r  = i / (KB / 4);
            int kc = (i % (KB / 4)) * 4;
            int gr = rowbase + r;
            float4 v = make_float4(0.f, 0.f, 0.f, 0.f);
            if (gr < n)
                v = *reinterpret_cast<const float4*>(A + (size_t)gr * D + kb + kc);
            As[r * LDA + kc + 0] = v.x;
            As[r * LDA + kc + 1] = v.y;
            As[r * LDA + kc + 2] = v.z;
            As[r * LDA + kc + 3] = v.w;
        }
        __syncthreads();
        #pragma unroll 8
        for (int k = 0; k < KB; k++) {
            float a0 = As[(rg * 4 + 0) * LDA + k];
            float a1 = As[(rg * 4 + 1) * LDA + k];
            float a2 = As[(rg * 4 + 2) * LDA + k];
            float a3 = As[(rg * 4 + 3) * LDA + k];
            const float* wr = Ws + (kb + k) * D + cg * 4;
            #pragma unroll
            for (int j4 = 0; j4 < 4; j4++) {
                float4 w = *reinterpret_cast<const float4*>(wr + j4 * (4 * COLG));
                acc[0][j4*4+0] += a0 * w.x; acc[0][j4*4+1] += a0 * w.y;
                acc[0][j4*4+2] += a0 * w.z; acc[0][j4*4+3] += a0 * w.w;
                acc[1][j4*4+0] += a1 * w.x; acc[1][j4*4+1] += a1 * w.y;
                acc[1][j4*4+2] += a1 * w.z; acc[1][j4*4+3] += a1 * w.w;
                acc[2][j4*4+0] += a2 * w.x; acc[2][j4*4+1] += a2 * w.y;
                acc[2][j4*4+2] += a2 * w.z; acc[2][j4*4+3] += a2 * w.w;
                acc[3][j4*4+0] += a3 * w.x; acc[3][j4*4+1] += a3 * w.y;
                acc[3][j4*4+2] += a3 * w.z; acc[3][j4*4+3] += a3 * w.w;
            }
        }
    }

    #pragma unroll
    for (int i = 0; i < 4; i++) {
        int gr = rowbase + rg * 4 + i;
        if (gr >= n) continue;
        #pragma unroll
        for (int j4 = 0; j4 < 4; j4++) {
            int c = cg * 4 + j4 * (4 * COLG);
            float4 v;
            v.x = acc[i][j4*4+0]; v.y = acc[i][j4*4+1];
            v.z = acc[i][j4*4+2]; v.w = acc[i][j4*4+3];
            if (bias) {
                v.x += bias[c+0]; v.y += bias[c+1];
                v.z += bias[c+2]; v.w += bias[c+3];
            }
            *reinterpret_cast<float4*>(C + (size_t)gr * D + c) = v;
        }
    }
}

// -------- merged GNA GEMM: [t | outb] = A[n,64] @ [W2 | W1], also ta = t.a --------
__global__ __launch_bounds__(256)
void gemm_gna(const float* __restrict__ A,
              const float* __restrict__ W2, const float* __restrict__ b2,
              const float* __restrict__ W1, const float* __restrict__ b1,
              const float* __restrict__ avec,
              float* __restrict__ T, float* __restrict__ O, int n)
{
    constexpr int DIN = 64, DOUT = 128, COLG = 8, BM = 128, LDA = DIN + 1;
    extern __shared__ float smem[];
    float* Ws = smem;                 // DIN*DOUT = 8192 floats
    float* As = smem + DIN * DOUT;    // BM*LDA   = 8320 floats

    const int tid = threadIdx.x;
    const int cg = tid & (COLG - 1);
    const int rg = tid >> 3;
    const int rowbase = blockIdx.x * BM;

    // stage Wcat = [W2 | W1] : Ws[k*128 + c]
    for (int i = tid; i < DIN * DOUT / 4; i += 256) {
        int k = i >> 5;
        int c = (i & 31) << 2;
        float4 v;
        if (c < 64) v = *reinterpret_cast<const float4*>(W2 + k * 64 + c);
        else        v = *reinterpret_cast<const float4*>(W1 + k * 64 + (c - 64));
        *reinterpret_cast<float4*>(Ws + k * DOUT + c) = v;
    }
    // stage A tile BM x 64
    for (int i = tid; i < BM * DIN / 4; i += 256) {
        int r  = i / (DIN / 4);
        int kc = (i % (DIN / 4)) * 4;
        int gr = rowbase + r;
        float4 v = make_float4(0.f, 0.f, 0.f, 0.f);
        if (gr < n)
            v = *reinterpret_cast<const float4*>(A + (size_t)gr * DIN + kc);
        As[r * LDA + kc + 0] = v.x;
        As[r * LDA + kc + 1] = v.y;
        As[r * LDA + kc + 2] = v.z;
        As[r * LDA + kc + 3] = v.w;
    }
    __syncthreads();

    float acc[4][16];
    #pragma unroll
    for (int i = 0; i < 4; i++)
        #pragma unroll
        for (int j = 0; j < 16; j++) acc[i][j] = 0.0f;

    #pragma unroll 8
    for (int k = 0; k < DIN; k++) {
        float a0 = As[(rg * 4 + 0) * LDA + k];
        float a1 = As[(rg * 4 + 1) * LDA + k];
        float a2 = As[(rg * 4 + 2) * LDA + k];
        float a3 = As[(rg * 4 + 3) * LDA + k];
        const float* wr = Ws + k * DOUT + cg * 4;
        #pragma unroll
        for (int j4 = 0; j4 < 4; j4++) {
            float4 w = *reinterpret_cast<const float4*>(wr + j4 * 32);
            acc[0][j4*4+0] += a0 * w.x; acc[0][j4*4+1] += a0 * w.y;
            acc[0][j4*4+2] += a0 * w.z; acc[0][j4*4+3] += a0 * w.w;
            acc[1][j4*4+0] += a1 * w.x; acc[1][j4*4+1] += a1 * w.y;
            acc[1][j4*4+2] += a1 * w.z; acc[1][j4*4+3] += a1 * w.w;
            acc[2][j4*4+0] += a2 * w.x; acc[2][j4*4+1] += a2 * w.y;
            acc[2][j4*4+2] += a2 * w.z; acc[2][j4*4+3] += a2 * w.w;
            acc[3][j4*4+0] += a3 * w.x; acc[3][j4*4+1] += a3 * w.y;
            acc[3][j4*4+2] += a3 * w.z; acc[3][j4*4+3] += a3 * w.w;
        }
    }

    // epilogue: t cols (j4=0,1) + ta reduce, outb cols (j4=2,3)
    #pragma unroll
    for (int i = 0; i < 4; i++) {
        int gr = rowbase + rg * 4 + i;
        float tap = 0.0f;
        #pragma unroll
        for (int j4 = 0; j4 < 2; j4++) {
            int c = cg * 4 + j4 * 32;
            float4 v;
            v.x = acc[i][j4*4+0] + b2[c+0];
            v.y = acc[i][j4*4+1] + b2[c+1];
            v.z = acc[i][j4*4+2] + b2[c+2];
            v.w = acc[i][j4*4+3] + b2[c+3];
            tap += v.x * avec[c+0] + v.y * avec[c+1]
                 + v.z * avec[c+2] + v.w * avec[c+3];
            if (gr < n)
                *reinterpret_cast<float4*>(T + (size_t)gr * SD + c) = v;
        }
        #pragma unroll
        for (int j4 = 2; j4 < 4; j4++) {
            int c = cg * 4 + j4 * 32 - 64;
            float4 v;
            v.x = acc[i][j4*4+0] + b1[c+0];
            v.y = acc[i][j4*4+1] + b1[c+1];
            v.z = acc[i][j4*4+2] + b1[c+2];
            v.w = acc[i][j4*4+3] + b1[c+3];
            if (gr < n)
                *reinterpret_cast<float4*>(O + (size_t)gr * SD + c) = v;
        }
        #pragma unroll
        for (int o = 1; o < 8; o <<= 1)
            tap += __shfl_xor_sync(0xffffffffu, tap, o);
        if (cg == 0 && gr < n) d_ta[gr] = tap;
    }
}

// ---------------- GCN aggregation: warp per dst node, gather-only ----------------
__global__ __launch_bounds__(256)
void k_gcn_agg(const float* __restrict__ h2, const float* __restrict__ bias,
               float* __restrict__ outp, int n, int dogelu)
{
    int gid = blockIdx.x * blockDim.x + threadIdx.x;
    int v = gid >> 5;
    if (v >= n) return;
    int lane = gid & 31;
    int c = lane << 2;

    int beg = d_rowptr[v];
    int end = d_rowptr[v + 1];
    float di = d_dinv[v];
    float di2 = di * di;

    float4 acc = *reinterpret_cast<const float4*>(h2 + (size_t)v * AD + c);
    float4 bs  = *reinterpret_cast<const float4*>(bias + c);
    acc.x = bs.x + di2 * acc.x;
    acc.y = bs.y + di2 * acc.y;
    acc.z = bs.z + di2 * acc.z;
    acc.w = bs.w + di2 * acc.w;

    for (int e = beg; e < end; e++) {
        int src  = d_esrc[e];
        float nv = d_enorm[e];
        float4 h = *reinterpret_cast<const float4*>(h2 + (size_t)src * AD + c);
        acc.x += nv * h.x; acc.y += nv * h.y;
        acc.z += nv * h.z; acc.w += nv * h.w;
    }

    if (dogelu) {
        acc.x = gelu_exact(acc.x); acc.y = gelu_exact(acc.y);
        acc.z = gelu_exact(acc.z); acc.w = gelu_exact(acc.w);
    }
    *reinterpret_cast<float4*>(outp + (size_t)v * AD + c) = acc;
}

// ---------------- GNA attention aggregation: warp per dst node ----------------
__global__ __launch_bounds__(256)
void k_gna_agg(float* __restrict__ gout, int n)
{
    int gid = blockIdx.x * blockDim.x + threadIdx.x;
    int v = gid >> 5;
    if (v >= n) return;
    int lane = gid & 31;

    int beg = d_rowptr[v];
    int end = d_rowptr[v + 1];
    float tav = d_ta[v];

    float m = 0.0f;
    for (int e = beg + lane; e < end; e += 32)
        m = fmaxf(m, tav - d_ta[d_esrc[e]]);
    #pragma unroll
    for (int o = 16; o; o >>= 1) m = fmaxf(m, __shfl_xor_sync(0xffffffffu, m, o));

    float a0 = 0.0f, a1 = 0.0f, denom = 0.0f;
    for (int e = beg; e < end; e++) {
        int src = d_esrc[e];
        float wgt = expf(tav - d_ta[src] - m);
        denom += wgt;
        a0 += wgt * d_t[(size_t)src * SD + lane];
        a1 += wgt * d_t[(size_t)src * SD + 32 + lane];
    }
    float wself = expf(-m);
    denom += wself;
    a0 += wself * d_t[(size_t)v * SD + lane];
    a1 += wself * d_t[(size_t)v * SD + 32 + lane];

    float inv = 1.0f / (denom + 1e-16f);
    size_t o = (size_t)v * SD;
    gout[o + lane]      = gelu_exact(d_outb[o + lane]      + a0 * inv);
    gout[o + 32 + lane] = gelu_exact(d_outb[o + 32 + lane] + a1 * inv);
}

// ---------------- host orchestration ----------------
extern "C" void kernel_launch(void* const* d_in, const int* in_sizes, int n_in,
                              void* d_out, int out_size) {
    const float* x     = (const float*)d_in[0];
    const float* s     = (const float*)d_in[1];
    const void*  ei    = (const void*)d_in[2];
    const float* gcn_W = (const float*)d_in[3];
    const float* gcn_b = (const float*)d_in[4];
    const float* w1W   = (const float*)d_in[5];
    const float* w1b   = (const float*)d_in[6];
    const float* w2W   = (const float*)d_in[7];
    const float* w2b   = (const float*)d_in[8];
    const float* ga    = (const float*)d_in[9];
    float* outp = (float*)d_out;

    const int n = in_sizes[0] / AD;
    const int E = in_sizes[2] / 2;

    void *p_h2, *p_hbuf, *p_t, *p_outb, *p_gbuf;
    cudaGetSymbolAddress(&p_h2,   d_h2);
    cudaGetSymbolAddress(&p_hbuf, d_hbuf);
    cudaGetSymbolAddress(&p_t,    d_t);
    cudaGetSymbolAddress(&p_outb, d_outb);
    cudaGetSymbolAddress(&p_gbuf, d_gbuf);

    const int SM128 = AD * AD * 4 + 128 * 33 * 4;     // 82432 B
    const int SMGNA = (64 * 128 + 128 * 65) * 4;      // 66048 B
    cudaFuncSetAttribute(gemm_kernel<128,32>, cudaFuncAttributeMaxDynamicSharedMemorySize, SM128);
    cudaFuncSetAttribute(gemm_gna,            cudaFuncAttributeMaxDynamicSharedMemorySize, SMGNA);

    // lazily-created side stream + fork/join events (persist across calls;
    // work per call is identical and fully captured)
    static cudaStream_t s2 = nullptr;
    static cudaEvent_t evF = nullptr, evJ = nullptr;
    if (!s2) {
        cudaStreamCreateWithFlags(&s2, cudaStreamNonBlocking);
        cudaEventCreateWithFlags(&evF, cudaEventDisableTiming);
        cudaEventCreateWithFlags(&evJ, cudaEventDisableTiming);
    }

    const int TB = 256;
    auto gb = [](int total, int tb) { return (total + tb - 1) / tb; };

    // ---- setup: dtype probe, degrees, dinv, CSR build (main stream) ----
    k_detect<<<1, 256>>>((const int*)ei, E);
    k_zero<<<gb(n, TB), TB>>>(n);
    k_prep<<<gb(E, TB), TB>>>(ei, E);
    k_dinv<<<gb(n, TB), TB>>>(n);
    int nscan = gb(n, 1024);
    k_scan1<<<nscan, 1024>>>(n);
    k_scan2<<<1, 64>>>(nscan);
    k_scan3<<<gb(n, TB), TB>>>(n);
    k_fill<<<gb(E, TB), TB>>>(E);

    // ---- fork: GNA branch runs on s2, GCN branch on main stream ----
    cudaEventRecord(evF, 0);
    cudaStreamWaitEvent(s2, evF, 0);

    // GCN branch (main stream)
    const float* hcur = x;
    for (int i = 0; i < NLAYERS; i++) {
        gemm_kernel<128,32><<<gb(n, 128), 256, SM128>>>(
            hcur, gcn_W + (size_t)i * AD * AD, nullptr, (float*)p_h2, n);
        float* aggout = (i == NLAYERS - 1) ? outp : (float*)p_hbuf;
        k_gcn_agg<<<gb(n * 32, TB), TB>>>((const float*)p_h2,
                                          gcn_b + (size_t)i * AD,
                                          aggout, n, (i < NLAYERS - 1) ? 1 : 0);
        hcur = (const float*)p_hbuf;
    }

    // GNA branch (stream s2)
    const float* gcur = s;
    for (int i = 0; i < NLAYERS; i++) {
        gemm_gna<<<gb(n, 128), 256, SMGNA, s2>>>(
            gcur,
            w2W + (size_t)i * SD * SD, w2b + (size_t)i * SD,
            w1W + (size_t)i * SD * SD, w1b + (size_t)i * SD,
            ga  + (size_t)i * SD,
            (float*)p_t, (float*)p_outb, n);
        float* gout = (i == NLAYERS - 1) ? (outp + (size_t)n * AD) : (float*)p_gbuf;
        k_gna_agg<<<gb(n * 32, TB), TB, 0, s2>>>(gout, n);
        gcur = (const float*)p_gbuf;
    }

    // ---- join ----
    cudaEventRecord(evJ, s2);
    cudaStreamWaitEvent(0, evJ, 0);
}

// round 15
// speedup vs baseline: 1.2806x; 1.0091x over previous
#include <cuda_runtime.h>
#include <math.h>

#define AD 128
#define SD 64
#define NLAYERS 4
#define MAXN 50000
#define MAXE 800000

typedef unsigned long long u64;

// ---------------- device scratch (no allocation allowed) ----------------
__device__ float d_h2[MAXN * AD];      // GEMM output (GCN)
__device__ float d_hbuf[MAXN * AD];    // GCN layer activation
__device__ float d_t[MAXN * SD];       // w2(g)
__device__ float d_outb[MAXN * SD];    // w1(g)
__device__ float d_gbuf[MAXN * SD];    // GNA layer activation
__device__ float d_ta[MAXN];           // t . a
__device__ float d_dinv[MAXN];
__device__ int   d_deg[MAXN];
__device__ int   d_fill[MAXN];
__device__ int   d_row[MAXE];
__device__ int   d_col[MAXE];
__device__ int   d_esrc[MAXE];         // CSR: src node of each edge, grouped by dst
__device__ float d_enorm[MAXE];        // CSR-ordered GCN norm
__device__ int   d_rowptr[MAXN + 1];
__device__ int   d_bsum[64];
__device__ int   d_is64;               // edge_index dtype flag (1 = int64, 0 = int32)

// ---------------- helpers ----------------
__device__ __forceinline__ float gelu_exact(float x) {
    return 0.5f * x * (1.0f + erff(x * 0.7071067811865475f));
}

// packed f32x2 FMA (Blackwell FFMA2 path — only reachable via PTX)
__device__ __forceinline__ u64 ffma2(u64 a, u64 b, u64 c) {
    u64 d;
    asm("fma.rn.f32x2 %0, %1, %2, %3;" : "=l"(d) : "l"(a), "l"(b), "l"(c));
    return d;
}
__device__ __forceinline__ u64 pack2(float x) {
    u64 d;
    unsigned xi = __float_as_uint(x);
    asm("mov.b64 %0, {%1, %1};" : "=l"(d) : "r"(xi));
    return d;
}
__device__ __forceinline__ float2 unpack2(u64 v) {
    unsigned lo, hi;
    asm("mov.b64 {%0, %1}, %2;" : "=r"(lo), "=r"(hi) : "l"(v));
    return make_float2(__uint_as_float(lo), __uint_as_float(hi));
}

// ---------------- setup kernels ----------------
__global__ void k_detect(const int* __restrict__ ei32, int E) {
    __shared__ int found;
    if (threadIdx.x == 0) found = 0;
    __syncthreads();
    int nz = 0;
    int samples = (E < 4096) ? E : 4096;
    for (int i = threadIdx.x; i < samples; i += blockDim.x)
        if (ei32[2 * i + 1] != 0) nz = 1;
    if (__syncthreads_or(nz)) { if (threadIdx.x == 0) found = 1; }
    __syncthreads();
    if (threadIdx.x == 0) d_is64 = found ? 0 : 1;
}

__global__ void k_zero(int n) {
    int i = blockIdx.x * blockDim.x + threadIdx.x;
    if (i < n) { d_deg[i] = 0; d_fill[i] = 0; }
}

__global__ void k_prep(const void* __restrict__ ei, int E) {
    int e = blockIdx.x * blockDim.x + threadIdx.x;
    if (e >= E) return;
    int r, c;
    if (d_is64) {
        const long long* p = (const long long*)ei;
        r = (int)p[e];
        c = (int)p[E + e];
    } else {
        const int* p = (const int*)ei;
        r = p[e];
        c = p[E + e];
    }
    d_row[e] = r;
    d_col[e] = c;
    atomicAdd(&d_deg[c], 1);
}

__global__ void k_dinv(int n) {
    int i = blockIdx.x * blockDim.x + threadIdx.x;
    if (i < n) d_dinv[i] = rsqrtf((float)d_deg[i] + 1.0f);   // +1 for self loop
}

__global__ void k_scan1(int n) {
    __shared__ int sm[1024];
    int i = blockIdx.x * 1024 + threadIdx.x;
    int v = (i < n) ? d_deg[i] : 0;
    sm[threadIdx.x] = v;
    __syncthreads();
    for (int off = 1; off < 1024; off <<= 1) {
        int t = (threadIdx.x >= off) ? sm[threadIdx.x - off] : 0;
        __syncthreads();
        sm[threadIdx.x] += t;
        __syncthreads();
    }
    if (i < n) d_rowptr[i + 1] = sm[threadIdx.x];
    if (threadIdx.x == 1023) d_bsum[blockIdx.x] = sm[1023];
}

__global__ void k_scan2(int nb) {
    if (threadIdx.x == 0) {
        int acc = 0;
        for (int b = 0; b < nb; b++) { int v = d_bsum[b]; d_bsum[b] = acc; acc += v; }
        d_rowptr[0] = 0;
    }
}

__global__ void k_scan3(int n) {
    int i = blockIdx.x * blockDim.x + threadIdx.x;
    if (i < n) d_rowptr[i + 1] += d_bsum[i >> 10];
}

__global__ void k_fill(int E) {
    int e = blockIdx.x * blockDim.x + threadIdx.x;
    if (e >= E) return;
    int r = d_row[e];
    int c = d_col[e];
    int pos = d_rowptr[c] + atomicAdd(&d_fill[c], 1);
    d_esrc[pos]  = r;
    d_enorm[pos] = d_dinv[r] * d_dinv[c];
}

// ------- GCN GEMM via packed f32x2 (FFMA2): C[n,128] = A[n,128] @ W[128,128] -------
__global__ __launch_bounds__(256)
void gemm_gcn(const float* __restrict__ A, const float* __restrict__ W,
              float* __restrict__ C, int n)
{
    constexpr int D = 128, KB = 32, COLG = 8, BM = 128, LDA = KB + 1;
    extern __shared__ float smem[];
    float* Ws = smem;                   // 128*128
    float* As = smem + D * D;           // 128*33

    const int tid = threadIdx.x;
    const int cg = tid & 7;
    const int rg = tid >> 3;
    const int rowbase = blockIdx.x * BM;

    {
        const float4* Wg = reinterpret_cast<const float4*>(W);
        float4* Wsm = reinterpret_cast<float4*>(Ws);
        for (int i = tid; i < D * D / 4; i += 256) Wsm[i] = Wg[i];
    }

    u64 acc2[4][8];
    #pragma unroll
    for (int i = 0; i < 4; i++)
        #pragma unroll
        for (int j = 0; j < 8; j++) acc2[i][j] = 0ull;

    for (int kb = 0; kb < D; kb += KB) {
        __syncthreads();
        for (int i = tid; i < BM * KB / 4; i += 256) {
            int r  = i / (KB / 4);
            int kc = (i % (KB / 4)) * 4;
            int gr = rowbase + r;
            float4 v = make_float4(0.f, 0.f, 0.f, 0.f);
            if (gr < n)
                v = *reinterpret_cast<const float4*>(A + (size_t)gr * D + kb + kc);
            As[r * LDA + kc + 0] = v.x;
            As[r * LDA + kc + 1] = v.y;
            As[r * LDA + kc + 2] = v.z;
            As[r * LDA + kc + 3] = v.w;
        }
        __syncthreads();
        #pragma unroll 4
        for (int k = 0; k < KB; k++) {
            u64 a2[4];
            a2[0] = pack2(As[(rg * 4 + 0) * LDA + k]);
            a2[1] = pack2(As[(rg * 4 + 1) * LDA + k]);
            a2[2] = pack2(As[(rg * 4 + 2) * LDA + k]);
            a2[3] = pack2(As[(rg * 4 + 3) * LDA + k]);
            const double2* wr = reinterpret_cast<const double2*>(Ws + (kb + k) * D + cg * 4);
            #pragma unroll
            for (int j4 = 0; j4 < 4; j4++) {
                double2 wv = wr[j4 * 8];               // +32 floats per j4
                u64 w0 = __double_as_longlong(wv.x);
                u64 w1 = __double_as_longlong(wv.y);
                #pragma unroll
                for (int i = 0; i < 4; i++) {
                    acc2[i][j4 * 2 + 0] = ffma2(a2[i], w0, acc2[i][j4 * 2 + 0]);
                    acc2[i][j4 * 2 + 1] = ffma2(a2[i], w1, acc2[i][j4 * 2 + 1]);
                }
            }
        }
    }

    #pragma unroll
    for (int i = 0; i < 4; i++) {
        int gr = rowbase + rg * 4 + i;
        if (gr >= n) continue;
        #pragma unroll
        for (int j4 = 0; j4 < 4; j4++) {
            int c = cg * 4 + j4 * 32;
            float2 p0 = unpack2(acc2[i][j4 * 2 + 0]);
            float2 p1 = unpack2(acc2[i][j4 * 2 + 1]);
            float4 v = make_float4(p0.x, p0.y, p1.x, p1.y);
            *reinterpret_cast<float4*>(C + (size_t)gr * D + c) = v;
        }
    }
}

// -------- merged GNA GEMM: [t | outb] = A[n,64] @ [W2 | W1], also ta = t.a --------
__global__ __launch_bounds__(256)
void gemm_gna(const float* __restrict__ A,
              const float* __restrict__ W2, const float* __restrict__ b2,
              const float* __restrict__ W1, const float* __restrict__ b1,
              const float* __restrict__ avec,
              float* __restrict__ T, float* __restrict__ O, int n)
{
    constexpr int DIN = 64, DOUT = 128, COLG = 8, BM = 128, LDA = DIN + 1;
    extern __shared__ float smem[];
    float* Ws = smem;                 // DIN*DOUT = 8192 floats
    float* As = smem + DIN * DOUT;    // BM*LDA   = 8320 floats

    const int tid = threadIdx.x;
    const int cg = tid & (COLG - 1);
    const int rg = tid >> 3;
    const int rowbase = blockIdx.x * BM;

    for (int i = tid; i < DIN * DOUT / 4; i += 256) {
        int k = i >> 5;
        int c = (i & 31) << 2;
        float4 v;
        if (c < 64) v = *reinterpret_cast<const float4*>(W2 + k * 64 + c);
        else        v = *reinterpret_cast<const float4*>(W1 + k * 64 + (c - 64));
        *reinterpret_cast<float4*>(Ws + k * DOUT + c) = v;
    }
    for (int i = tid; i < BM * DIN / 4; i += 256) {
        int r  = i / (DIN / 4);
        int kc = (i % (DIN / 4)) * 4;
        int gr = rowbase + r;
        float4 v = make_float4(0.f, 0.f, 0.f, 0.f);
        if (gr < n)
            v = *reinterpret_cast<const float4*>(A + (size_t)gr * DIN + kc);
        As[r * LDA + kc + 0] = v.x;
        As[r * LDA + kc + 1] = v.y;
        As[r * LDA + kc + 2] = v.z;
        As[r * LDA + kc + 3] = v.w;
    }
    __syncthreads();

    u64 acc2[4][8];
    #pragma unroll
    for (int i = 0; i < 4; i++)
        #pragma unroll
        for (int j = 0; j < 8; j++) acc2[i][j] = 0ull;

    #pragma unroll 4
    for (int k = 0; k < DIN; k++) {
        u64 a2[4];
        a2[0] = pack2(As[(rg * 4 + 0) * LDA + k]);
        a2[1] = pack2(As[(rg * 4 + 1) * LDA + k]);
        a2[2] = pack2(As[(rg * 4 + 2) * LDA + k]);
        a2[3] = pack2(As[(rg * 4 + 3) * LDA + k]);
        const double2* wr = reinterpret_cast<const double2*>(Ws + k * DOUT + cg * 4);
        #pragma unroll
        for (int j4 = 0; j4 < 4; j4++) {
            double2 wv = wr[j4 * 8];
            u64 w0 = __double_as_longlong(wv.x);
            u64 w1 = __double_as_longlong(wv.y);
            #pragma unroll
            for (int i = 0; i < 4; i++) {
                acc2[i][j4 * 2 + 0] = ffma2(a2[i], w0, acc2[i][j4 * 2 + 0]);
                acc2[i][j4 * 2 + 1] = ffma2(a2[i], w1, acc2[i][j4 * 2 + 1]);
            }
        }
    }

    // epilogue: t cols (j4=0,1) + ta reduce, outb cols (j4=2,3)
    #pragma unroll
    for (int i = 0; i < 4; i++) {
        int gr = rowbase + rg * 4 + i;
        float tap = 0.0f;
        #pragma unroll
        for (int j4 = 0; j4 < 2; j4++) {
            int c = cg * 4 + j4 * 32;
            float2 p0 = unpack2(acc2[i][j4 * 2 + 0]);
            float2 p1 = unpack2(acc2[i][j4 * 2 + 1]);
            float4 v;
            v.x = p0.x + b2[c+0];
            v.y = p0.y + b2[c+1];
            v.z = p1.x + b2[c+2];
            v.w = p1.y + b2[c+3];
            tap += v.x * avec[c+0] + v.y * avec[c+1]
                 + v.z * avec[c+2] + v.w * avec[c+3];
            if (gr < n)
                *reinterpret_cast<float4*>(T + (size_t)gr * SD + c) = v;
        }
        #pragma unroll
        for (int j4 = 2; j4 < 4; j4++) {
            int c = cg * 4 + j4 * 32 - 64;
            float2 p0 = unpack2(acc2[i][j4 * 2 + 0]);
            float2 p1 = unpack2(acc2[i][j4 * 2 + 1]);
            float4 v;
            v.x = p0.x + b1[c+0];
            v.y = p0.y + b1[c+1];
            v.z = p1.x + b1[c+2];
            v.w = p1.y + b1[c+3];
            if (gr < n)
                *reinterpret_cast<float4*>(O + (size_t)gr * SD + c) = v;
        }
        #pragma unroll
        for (int o = 1; o < 8; o <<= 1)
            tap += __shfl_xor_sync(0xffffffffu, tap, o);
        if (cg == 0 && gr < n) d_ta[gr] = tap;
    }
}

// ---------------- GCN aggregation: warp per dst node, gather-only ----------------
__global__ __launch_bounds__(256)
void k_gcn_agg(const float* __restrict__ h2, const float* __restrict__ bias,
               float* __restrict__ outp, int n, int dogelu)
{
    int gid = blockIdx.x * blockDim.x + threadIdx.x;
    int v = gid >> 5;
    if (v >= n) return;
    int lane = gid & 31;
    int c = lane << 2;

    int beg = d_rowptr[v];
    int end = d_rowptr[v + 1];
    float di = d_dinv[v];
    float di2 = di * di;

    float4 acc = *reinterpret_cast<const float4*>(h2 + (size_t)v * AD + c);
    float4 bs  = *reinterpret_cast<const float4*>(bias + c);
    acc.x = bs.x + di2 * acc.x;
    acc.y = bs.y + di2 * acc.y;
    acc.z = bs.z + di2 * acc.z;
    acc.w = bs.w + di2 * acc.w;

    for (int e = beg; e < end; e++) {
        int src  = d_esrc[e];
        float nv = d_enorm[e];
        float4 h = *reinterpret_cast<const float4*>(h2 + (size_t)src * AD + c);
        acc.x += nv * h.x; acc.y += nv * h.y;
        acc.z += nv * h.z; acc.w += nv * h.w;
    }

    if (dogelu) {
        acc.x = gelu_exact(acc.x); acc.y = gelu_exact(acc.y);
        acc.z = gelu_exact(acc.z); acc.w = gelu_exact(acc.w);
    }
    *reinterpret_cast<float4*>(outp + (size_t)v * AD + c) = acc;
}

// ---------------- GNA attention aggregation: warp per dst node ----------------
__global__ __launch_bounds__(256)
void k_gna_agg(float* __restrict__ gout, int n)
{
    int gid = blockIdx.x * blockDim.x + threadIdx.x;
    int v = gid >> 5;
    if (v >= n) return;
    int lane = gid & 31;

    int beg = d_rowptr[v];
    int end = d_rowptr[v + 1];
    float tav = d_ta[v];

    float m = 0.0f;
    for (int e = beg + lane; e < end; e += 32)
        m = fmaxf(m, tav - d_ta[d_esrc[e]]);
    #pragma unroll
    for (int o = 16; o; o >>= 1) m = fmaxf(m, __shfl_xor_sync(0xffffffffu, m, o));

    float a0 = 0.0f, a1 = 0.0f, denom = 0.0f;
    for (int e = beg; e < end; e++) {
        int src = d_esrc[e];
        float wgt = expf(tav - d_ta[src] - m);
        denom += wgt;
        a0 += wgt * d_t[(size_t)src * SD + lane];
        a1 += wgt * d_t[(size_t)src * SD + 32 + lane];
    }
    float wself = expf(-m);
    denom += wself;
    a0 += wself * d_t[(size_t)v * SD + lane];
    a1 += wself * d_t[(size_t)v * SD + 32 + lane];

    float inv = 1.0f / (denom + 1e-16f);
    size_t o = (size_t)v * SD;
    gout[o + lane]      = gelu_exact(d_outb[o + lane]      + a0 * inv);
    gout[o + 32 + lane] = gelu_exact(d_outb[o + 32 + lane] + a1 * inv);
}

// ---------------- host orchestration ----------------
extern "C" void kernel_launch(void* const* d_in, const int* in_sizes, int n_in,
                              void* d_out, int out_size) {
    const float* x     = (const float*)d_in[0];
    const float* s     = (const float*)d_in[1];
    const void*  ei    = (const void*)d_in[2];
    const float* gcn_W = (const float*)d_in[3];
    const float* gcn_b = (const float*)d_in[4];
    const float* w1W   = (const float*)d_in[5];
    const float* w1b   = (const float*)d_in[6];
    const float* w2W   = (const float*)d_in[7];
    const float* w2b   = (const float*)d_in[8];
    const float* ga    = (const float*)d_in[9];
    float* outp = (float*)d_out;

    const int n = in_sizes[0] / AD;
    const int E = in_sizes[2] / 2;

    void *p_h2, *p_hbuf, *p_t, *p_outb, *p_gbuf;
    cudaGetSymbolAddress(&p_h2,   d_h2);
    cudaGetSymbolAddress(&p_hbuf, d_hbuf);
    cudaGetSymbolAddress(&p_t,    d_t);
    cudaGetSymbolAddress(&p_outb, d_outb);
    cudaGetSymbolAddress(&p_gbuf, d_gbuf);

    const int SM128 = AD * AD * 4 + 128 * 33 * 4;     // 82432 B
    const int SMGNA = (64 * 128 + 128 * 65) * 4;      // 66048 B
    cudaFuncSetAttribute(gemm_gcn, cudaFuncAttributeMaxDynamicSharedMemorySize, SM128);
    cudaFuncSetAttribute(gemm_gna, cudaFuncAttributeMaxDynamicSharedMemorySize, SMGNA);

    // lazily-created side streams + fork/join events
    static cudaStream_t s2 = nullptr, s3 = nullptr;
    static cudaEvent_t evF = nullptr, evS = nullptr, evJ = nullptr;
    if (!s2) {
        cudaStreamCreateWithFlags(&s2, cudaStreamNonBlocking);
        cudaStreamCreateWithFlags(&s3, cudaStreamNonBlocking);
        cudaEventCreateWithFlags(&evF, cudaEventDisableTiming);
        cudaEventCreateWithFlags(&evS, cudaEventDisableTiming);
        cudaEventCreateWithFlags(&evJ, cudaEventDisableTiming);
    }

    const int TB = 256;
    auto gb = [](int total, int tb) { return (total + tb - 1) / tb; };

    // ---- fork: setup on s3, GNA on s2, GCN on main ----
    cudaEventRecord(evF, 0);
    cudaStreamWaitEvent(s3, evF, 0);
    cudaStreamWaitEvent(s2, evF, 0);

    // setup chain on s3 (only needed by the agg kernels)
    k_detect<<<1, 256, 0, s3>>>((const int*)ei, E);
    k_zero<<<gb(n, TB), TB, 0, s3>>>(n);
    k_prep<<<gb(E, TB), TB, 0, s3>>>(ei, E);
    k_dinv<<<gb(n, TB), TB, 0, s3>>>(n);
    int nscan = gb(n, 1024);
    k_scan1<<<nscan, 1024, 0, s3>>>(n);
    k_scan2<<<1, 64, 0, s3>>>(nscan);
    k_scan3<<<gb(n, TB), TB, 0, s3>>>(n);
    k_fill<<<gb(E, TB), TB, 0, s3>>>(E);
    cudaEventRecord(evS, s3);

    // GCN branch (main stream)
    const float* hcur = x;
    for (int i = 0; i < NLAYERS; i++) {
        gemm_gcn<<<gb(n, 128), 256, SM128>>>(
            hcur, gcn_W + (size_t)i * AD * AD, (float*)p_h2, n);
        if (i == 0) cudaStreamWaitEvent(0, evS, 0);   // agg needs CSR
        float* aggout = (i == NLAYERS - 1) ? outp : (float*)p_hbuf;
        k_gcn_agg<<<gb(n * 32, TB), TB>>>((const float*)p_h2,
                                          gcn_b + (size_t)i * AD,
                                          aggout, n, (i < NLAYERS - 1) ? 1 : 0);
        hcur = (const float*)p_hbuf;
    }

    // GNA branch (stream s2)
    const float* gcur = s;
    for (int i = 0; i < NLAYERS; i++) {
        gemm_gna<<<gb(n, 128), 256, SMGNA, s2>>>(
            gcur,
            w2W + (size_t)i * SD * SD, w2b + (size_t)i * SD,
            w1W + (size_t)i * SD * SD, w1b + (size_t)i * SD,
            ga  + (size_t)i * SD,
            (float*)p_t, (float*)p_outb, n);
        if (i == 0) cudaStreamWaitEvent(s2, evS, 0);  // agg needs CSR
        float* gout = (i == NLAYERS - 1) ? (outp + (size_t)n * AD) : (float*)p_gbuf;
        k_gna_agg<<<gb(n * 32, TB), TB, 0, s2>>>(gout, n);
        gcur = (const float*)p_gbuf;
    }

    // ---- join ----
    cudaEventRecord(evJ, s2);
    cudaStreamWaitEvent(0, evJ, 0);
}